// round 5
// baseline (speedup 1.0000x reference)
#include <cuda_runtime.h>
#include <cuda_bf16.h>
#include <cstdint>
#include <math.h>

// Problem dims
#define FDIM 2048
#define BDIM 2
#define HDIM 1024
#define NHEAD 16
#define EDIM 64
#define MROWS (FDIM * BDIM)      // 4096
#define N3 (3 * HDIM)            // 3072
#define MASK_ELEMS (BDIM * FDIM * FDIM)   // 8388608

// ---------------------------------------------------------------------------
// Device scratch
// ---------------------------------------------------------------------------
__device__ float g_q[(size_t)BDIM * NHEAD * FDIM * EDIM];
__device__ float g_k[(size_t)BDIM * NHEAD * FDIM * EDIM];
__device__ float g_v[(size_t)BDIM * NHEAD * FDIM * EDIM];
__device__ float g_ctx[(size_t)MROWS * HDIM];
__device__ unsigned char g_mask[(size_t)MASK_ELEMS];
__device__ int g_mask_is_u8;

// split-bf16 operands
__device__ __nv_bfloat16 gA_hi[(size_t)MROWS * HDIM];
__device__ __nv_bfloat16 gA_lo[(size_t)MROWS * HDIM];
__device__ __nv_bfloat16 gWqkv_hi[(size_t)N3 * HDIM];   // transposed [3072][1024]
__device__ __nv_bfloat16 gWqkv_lo[(size_t)N3 * HDIM];
__device__ __nv_bfloat16 gWout_hi[(size_t)HDIM * HDIM]; // transposed [d][ne]
__device__ __nv_bfloat16 gWout_lo[(size_t)HDIM * HDIM];
__device__ __nv_bfloat16 gCtx_hi[(size_t)MROWS * HDIM];
__device__ __nv_bfloat16 gCtx_lo[(size_t)MROWS * HDIM];

// ---------------------------------------------------------------------------
// mma.sync bf16 (baseline PTX feature, works on compute_103)
// ---------------------------------------------------------------------------
__device__ __forceinline__ void mma16816(float* d, const uint32_t* a,
                                         const uint32_t* b)
{
    asm volatile(
        "mma.sync.aligned.m16n8k16.row.col.f32.bf16.bf16.f32 "
        "{%0,%1,%2,%3}, {%4,%5,%6,%7}, {%8,%9}, {%0,%1,%2,%3};"
        : "+f"(d[0]), "+f"(d[1]), "+f"(d[2]), "+f"(d[3])
        : "r"(a[0]), "r"(a[1]), "r"(a[2]), "r"(a[3]), "r"(b[0]), "r"(b[1]));
}

// ---------------------------------------------------------------------------
// Mask canonicalization (uint8-bool or int32-bool -> uint8)
// ---------------------------------------------------------------------------
__global__ void detect_mask_kernel(const unsigned int* __restrict__ raw)
{
    __shared__ int found;
    if (threadIdx.x == 0) found = 0;
    __syncthreads();
    int local = 0;
    for (int i = threadIdx.x; i < 4096; i += blockDim.x)
        if (raw[i] > 1u) local = 1;
    if (local) atomicOr(&found, 1);
    __syncthreads();
    if (threadIdx.x == 0) g_mask_is_u8 = found;
}

__global__ void convert_mask_kernel(const void* __restrict__ raw)
{
    int i4 = blockIdx.x * blockDim.x + threadIdx.x;
    if (i4 >= MASK_ELEMS / 4) return;
    uchar4 o;
    if (g_mask_is_u8) {
        o = ((const uchar4*)raw)[i4];
        o.x = o.x ? 1 : 0; o.y = o.y ? 1 : 0; o.z = o.z ? 1 : 0; o.w = o.w ? 1 : 0;
    } else {
        int4 v = ((const int4*)raw)[i4];
        o.x = v.x ? 1 : 0; o.y = v.y ? 1 : 0; o.z = v.z ? 1 : 0; o.w = v.w ? 1 : 0;
    }
    ((uchar4*)g_mask)[i4] = o;
}

// ---------------------------------------------------------------------------
// fp32 -> bf16 hi/lo split (row-major, no transpose)
// ---------------------------------------------------------------------------
__global__ void split_kernel(const float* __restrict__ in,
                             __nv_bfloat16* __restrict__ hi,
                             __nv_bfloat16* __restrict__ lo, int n4)
{
    int i = blockIdx.x * blockDim.x + threadIdx.x;
    if (i >= n4) return;
    float4 v = ((const float4*)in)[i];
    float vv[4] = {v.x, v.y, v.z, v.w};
#pragma unroll
    for (int c = 0; c < 4; c++) {
        __nv_bfloat16 h = __float2bfloat16(vv[c]);
        __nv_bfloat16 l = __float2bfloat16(vv[c] - __bfloat162float(h));
        hi[4 * i + c] = h;
        lo[4 * i + c] = l;
    }
}

// fp32 [R][C] -> transposed bf16 hi/lo [C][R]
__global__ void tsplit_kernel(const float* __restrict__ in,
                              __nv_bfloat16* __restrict__ hiT,
                              __nv_bfloat16* __restrict__ loT, int R, int C)
{
    __shared__ float t[32][33];
    int c0 = blockIdx.x * 32, r0 = blockIdx.y * 32;
#pragma unroll
    for (int p = 0; p < 4; p++) {
        int r = r0 + threadIdx.y + p * 8;
        t[threadIdx.y + p * 8][threadIdx.x] = in[(size_t)r * C + c0 + threadIdx.x];
    }
    __syncthreads();
#pragma unroll
    for (int p = 0; p < 4; p++) {
        int c = c0 + threadIdx.y + p * 8;      // output row
        float v = t[threadIdx.x][threadIdx.y + p * 8];
        __nv_bfloat16 h = __float2bfloat16(v);
        __nv_bfloat16 l = __float2bfloat16(v - __bfloat162float(h));
        size_t o = (size_t)c * R + r0 + threadIdx.x;
        hiT[o] = h;
        loT[o] = l;
    }
}

// ---------------------------------------------------------------------------
// mma.sync split-bf16 GEMM: C[M,N] = A[M,K] * B^T (B stored [N][K] row-major)
// CTA tile 128x64, 256 threads, 8 warps (4 M x 2 N), warp tile 32x32.
// 3 product passes per k16: Ahi*Bhi + Ahi*Blo + Alo*Bhi, fp32 accum.
// EPI==0: scatter + bias into g_q/g_k/g_v.  EPI==1: dense C (no bias).
// ---------------------------------------------------------------------------
#define ASTR 72   // bf16 stride (padded) for 64-wide k-chunk tiles
#define GEMM_SMEM_BYTES ((128 * ASTR * 2 + 64 * ASTR * 2) * 2)   // 55296

template <int EPI>
__global__ __launch_bounds__(256) void gemm_mma(
    const __nv_bfloat16* __restrict__ Ahi, const __nv_bfloat16* __restrict__ Alo,
    const __nv_bfloat16* __restrict__ Bhi, const __nv_bfloat16* __restrict__ Blo,
    const float* __restrict__ bias, float* __restrict__ C,
    int Nn, int K)
{
    extern __shared__ __nv_bfloat16 sm_bf[];
    __nv_bfloat16* sAh = sm_bf;                  // [128][72]
    __nv_bfloat16* sAl = sAh + 128 * ASTR;
    __nv_bfloat16* sBh = sAl + 128 * ASTR;       // [64][72]
    __nv_bfloat16* sBl = sBh + 64 * ASTR;

    const int tid = threadIdx.x;
    const int wid = tid >> 5, lane = tid & 31;
    const int grp = lane >> 2, tig = lane & 3;
    const int wm = wid & 3, wn = wid >> 2;       // warp grid 4 (M) x 2 (N)
    const int m0 = blockIdx.y * 128, n0 = blockIdx.x * 64;

    float acc[2][4][4];
#pragma unroll
    for (int mt = 0; mt < 2; mt++)
#pragma unroll
        for (int nt = 0; nt < 4; nt++)
#pragma unroll
            for (int r = 0; r < 4; r++) acc[mt][nt][r] = 0.0f;

    const int arow = tid >> 1, ahalf = (tid & 1) * 32;   // A: 128 rows x 64
    const int brow = tid >> 2, bq = (tid & 3) * 16;      // B: 64 rows x 64

    for (int k0 = 0; k0 < K; k0 += 64) {
        // ---- global -> smem ----
        {
            const uint4* ga = (const uint4*)(Ahi + (size_t)(m0 + arow) * K + k0 + ahalf);
            const uint4* gl = (const uint4*)(Alo + (size_t)(m0 + arow) * K + k0 + ahalf);
            uint4* da = (uint4*)(sAh + arow * ASTR + ahalf);
            uint4* dl = (uint4*)(sAl + arow * ASTR + ahalf);
#pragma unroll
            for (int i = 0; i < 4; i++) { da[i] = ga[i]; dl[i] = gl[i]; }

            const uint4* gb = (const uint4*)(Bhi + (size_t)(n0 + brow) * K + k0 + bq);
            const uint4* gbl = (const uint4*)(Blo + (size_t)(n0 + brow) * K + k0 + bq);
            uint4* db = (uint4*)(sBh + brow * ASTR + bq);
            uint4* dbl = (uint4*)(sBl + brow * ASTR + bq);
#pragma unroll
            for (int i = 0; i < 2; i++) { db[i] = gb[i]; dbl[i] = gbl[i]; }
        }
        __syncthreads();

        // ---- 4 k16 steps ----
#pragma unroll
        for (int kk = 0; kk < 4; kk++) {
            const int kb = kk * 16;
            uint32_t ah[2][4], al[2][4];
#pragma unroll
            for (int mt = 0; mt < 2; mt++) {
                int r = wm * 32 + mt * 16 + grp;
                int o00 = r * ASTR + kb + tig * 2;
                int o10 = (r + 8) * ASTR + kb + tig * 2;
                ah[mt][0] = *(const uint32_t*)(sAh + o00);
                ah[mt][1] = *(const uint32_t*)(sAh + o10);
                ah[mt][2] = *(const uint32_t*)(sAh + o00 + 8);
                ah[mt][3] = *(const uint32_t*)(sAh + o10 + 8);
                al[mt][0] = *(const uint32_t*)(sAl + o00);
                al[mt][1] = *(const uint32_t*)(sAl + o10);
                al[mt][2] = *(const uint32_t*)(sAl + o00 + 8);
                al[mt][3] = *(const uint32_t*)(sAl + o10 + 8);
            }
            uint32_t bh[4][2], bl[4][2];
#pragma unroll
            for (int nt = 0; nt < 4; nt++) {
                int n = wn * 32 + nt * 8 + grp;
                int o = n * ASTR + kb + tig * 2;
                bh[nt][0] = *(const uint32_t*)(sBh + o);
                bh[nt][1] = *(const uint32_t*)(sBh + o + 8);
                bl[nt][0] = *(const uint32_t*)(sBl + o);
                bl[nt][1] = *(const uint32_t*)(sBl + o + 8);
            }
#pragma unroll
            for (int mt = 0; mt < 2; mt++)
#pragma unroll
                for (int nt = 0; nt < 4; nt++) {
                    mma16816(acc[mt][nt], ah[mt], bh[nt]);
                    mma16816(acc[mt][nt], ah[mt], bl[nt]);
                    mma16816(acc[mt][nt], al[mt], bh[nt]);
                }
        }
        __syncthreads();
    }

    // ---- epilogue ----
#pragma unroll
    for (int mt = 0; mt < 2; mt++) {
#pragma unroll
        for (int nt = 0; nt < 4; nt++) {
            int rbase = m0 + wm * 32 + mt * 16 + grp;
            int cbase = n0 + wn * 32 + nt * 8 + tig * 2;
#pragma unroll
            for (int half = 0; half < 2; half++) {   // row, row+8
                int m = rbase + half * 8;
                float v0 = acc[mt][nt][half * 2 + 0];
                float v1 = acc[mt][nt][half * 2 + 1];
                if (EPI == 0) {
                    int f = m >> 1, bb = m & 1;
#pragma unroll
                    for (int cc = 0; cc < 2; cc++) {
                        int d = cbase + cc;
                        int nh = d / 192;
                        int rr = d - nh * 192;
                        int kind = rr >> 6, e = rr & 63;
                        float val = (cc ? v1 : v0) + __ldg(bias + d);
                        float* dst = (kind == 0) ? g_q : (kind == 1) ? g_k : g_v;
                        dst[(((bb << 4) + nh) * FDIM + f) * EDIM + e] = val;
                    }
                } else {
                    *(float2*)(C + (size_t)m * Nn + cbase) = make_float2(v0, v1);
                }
            }
        }
    }
}

// ---------------------------------------------------------------------------
// Flash attention (unchanged SIMT version; round-5 target)
// ---------------------------------------------------------------------------
#define QS_STR 65
#define KS_STR 65
#define VS_STR 68
#define PS_STR 68
#define ATTN_SMEM_FLOATS (128 * QS_STR + 64 * KS_STR + 64 * VS_STR + 128 * PS_STR)
#define ATTN_SMEM_BYTES (ATTN_SMEM_FLOATS * 4)

__global__ __launch_bounds__(256) void attn_kernel(float* __restrict__ ctxout)
{
    extern __shared__ float sm[];
    float* Qs = sm;
    float* Ks = Qs + 128 * QS_STR;
    float* Vs = Ks + 64 * KS_STR;
    float* Ps = Vs + 64 * VS_STR;

    const int tid = threadIdx.x;
    const int tx = tid & 15, ty = tid >> 4;
    const int head = blockIdx.y;
    const int b = head >> 4, n = head & 15;
    const int f0 = blockIdx.x * 128;

    const float* qh = g_q + (size_t)head * FDIM * EDIM;
    const float* kh = g_k + (size_t)head * FDIM * EDIM;
    const float* vh = g_v + (size_t)head * FDIM * EDIM;
    const unsigned char* mbase = g_mask + (size_t)b * FDIM * FDIM;

#pragma unroll
    for (int p = 0; p < 8; p++) {
        int L = p * 256 + tid;
        int r = L >> 4, c4 = (L & 15) << 2;
        float4 v = *(const float4*)(qh + (f0 + r) * EDIM + c4);
        Qs[r * QS_STR + c4 + 0] = v.x * 0.125f;
        Qs[r * QS_STR + c4 + 1] = v.y * 0.125f;
        Qs[r * QS_STR + c4 + 2] = v.z * 0.125f;
        Qs[r * QS_STR + c4 + 3] = v.w * 0.125f;
    }

    float mrow[8], lrow[8], cacc[8][4];
#pragma unroll
    for (int i = 0; i < 8; i++) {
        mrow[i] = -1e30f;
        lrow[i] = 0.0f;
#pragma unroll
        for (int j = 0; j < 4; j++) cacc[i][j] = 0.0f;
    }

    for (int t0 = 0; t0 < FDIM; t0 += 64) {
#pragma unroll
        for (int p = 0; p < 4; p++) {
            int L = p * 256 + tid;
            int r = L >> 4, c4 = (L & 15) << 2;
            float4 kv = *(const float4*)(kh + (t0 + r) * EDIM + c4);
            Ks[r * KS_STR + c4 + 0] = kv.x;
            Ks[r * KS_STR + c4 + 1] = kv.y;
            Ks[r * KS_STR + c4 + 2] = kv.z;
            Ks[r * KS_STR + c4 + 3] = kv.w;
            float4 vv = *(const float4*)(vh + (t0 + r) * EDIM + c4);
            *(float4*)&Vs[r * VS_STR + c4] = vv;
        }
        __syncthreads();

        float s[8][4];
#pragma unroll
        for (int i = 0; i < 8; i++)
#pragma unroll
            for (int j = 0; j < 4; j++) s[i][j] = 0.0f;

#pragma unroll 8
        for (int e = 0; e < 64; e++) {
            float kr0 = Ks[(tx * 4 + 0) * KS_STR + e];
            float kr1 = Ks[(tx * 4 + 1) * KS_STR + e];
            float kr2 = Ks[(tx * 4 + 2) * KS_STR + e];
            float kr3 = Ks[(tx * 4 + 3) * KS_STR + e];
#pragma unroll
            for (int i = 0; i < 8; i++) {
                float qv = Qs[(ty * 8 + i) * QS_STR + e];
                s[i][0] += qv * kr0;
                s[i][1] += qv * kr1;
                s[i][2] += qv * kr2;
                s[i][3] += qv * kr3;
            }
        }

#pragma unroll
        for (int i = 0; i < 8; i++) {
            int f = f0 + ty * 8 + i;
            uchar4 mv = *(const uchar4*)(mbase + (size_t)f * FDIM + t0 + tx * 4);
            if (!mv.x) s[i][0] = -10000.0f;
            if (!mv.y) s[i][1] = -10000.0f;
            if (!mv.z) s[i][2] = -10000.0f;
            if (!mv.w) s[i][3] = -10000.0f;

            float mt = fmaxf(fmaxf(s[i][0], s[i][1]), fmaxf(s[i][2], s[i][3]));
#pragma unroll
            for (int o = 1; o < 16; o <<= 1)
                mt = fmaxf(mt, __shfl_xor_sync(0xffffffffu, mt, o));

            float mnew = fmaxf(mrow[i], mt);
            float corr = __expf(mrow[i] - mnew);
            mrow[i] = mnew;

            float ps = 0.0f;
#pragma unroll
            for (int j = 0; j < 4; j++) {
                s[i][j] = __expf(s[i][j] - mnew);
                ps += s[i][j];
            }
#pragma unroll
            for (int o = 1; o < 16; o <<= 1)
                ps += __shfl_xor_sync(0xffffffffu, ps, o);

            lrow[i] = lrow[i] * corr + ps;
#pragma unroll
            for (int j = 0; j < 4; j++) cacc[i][j] *= corr;

#pragma unroll
            for (int j = 0; j < 4; j++)
                Ps[(ty * 8 + i) * PS_STR + tx * 4 + j] = s[i][j];
        }
        __syncthreads();

#pragma unroll 8
        for (int t = 0; t < 64; t++) {
            float4 vv = *(const float4*)&Vs[t * VS_STR + tx * 4];
#pragma unroll
            for (int i = 0; i < 8; i++) {
                float pv = Ps[(ty * 8 + i) * PS_STR + t];
                cacc[i][0] += pv * vv.x;
                cacc[i][1] += pv * vv.y;
                cacc[i][2] += pv * vv.z;
                cacc[i][3] += pv * vv.w;
            }
        }
        __syncthreads();
    }

#pragma unroll
    for (int i = 0; i < 8; i++) {
        float inv = 1.0f / lrow[i];
        int f = f0 + ty * 8 + i;
        float4 o = make_float4(cacc[i][0] * inv, cacc[i][1] * inv,
                               cacc[i][2] * inv, cacc[i][3] * inv);
        *(float4*)(ctxout + ((size_t)f * BDIM + b) * HDIM + n * EDIM + tx * 4) = o;
    }
}

__global__ void tail_kernel(const float* __restrict__ b_out,
                            float* __restrict__ dst, int nvals)
{
    int i = blockIdx.x * blockDim.x + threadIdx.x;
    if (i < nvals) dst[i] = b_out[i];
}

extern "C" void kernel_launch(void* const* d_in, const int* in_sizes, int n_in,
                              void* d_out, int out_size)
{
    // Identify inputs by unique element counts
    const float* q_input = nullptr;
    const void* mask_raw = nullptr;
    const float* w_qkv = nullptr;
    const float* b_qkv = nullptr;
    const float* w_out = nullptr;
    const float* b_out = nullptr;
    for (int i = 0; i < n_in; i++) {
        switch (in_sizes[i]) {
            case 4194304: q_input = (const float*)d_in[i]; break;
            case 8388608: mask_raw = d_in[i]; break;
            case 3145728: w_qkv = (const float*)d_in[i]; break;
            case 3072:    b_qkv = (const float*)d_in[i]; break;
            case 1048576: w_out = (const float*)d_in[i]; break;
            case 1024:    b_out = (const float*)d_in[i]; break;
            default: break;
        }
    }
    float* out = (float*)d_out;

    cudaFuncSetAttribute(attn_kernel, cudaFuncAttributeMaxDynamicSharedMemorySize,
                         ATTN_SMEM_BYTES);
    cudaFuncSetAttribute(gemm_mma<0>, cudaFuncAttributeMaxDynamicSharedMemorySize,
                         GEMM_SMEM_BYTES);
    cudaFuncSetAttribute(gemm_mma<1>, cudaFuncAttributeMaxDynamicSharedMemorySize,
                         GEMM_SMEM_BYTES);

    // 0) Mask canonicalization
    detect_mask_kernel<<<1, 256>>>((const unsigned int*)mask_raw);
    convert_mask_kernel<<<(MASK_ELEMS / 4 + 255) / 256, 256>>>(mask_raw);

    // 0b) Operand conversions: split fp32 -> bf16 hi/lo (+ transpose for weights)
    split_kernel<<<(MROWS * HDIM / 4 + 255) / 256, 256>>>(q_input, gA_hi, gA_lo,
                                                          MROWS * HDIM / 4);
    tsplit_kernel<<<dim3(N3 / 32, HDIM / 32), dim3(32, 8)>>>(w_qkv, gWqkv_hi, gWqkv_lo,
                                                             HDIM, N3);
    tsplit_kernel<<<dim3(HDIM / 32, HDIM / 32), dim3(32, 8)>>>(w_out, gWout_hi, gWout_lo,
                                                               HDIM, HDIM);

    // 1) QKV projection on tensor cores (mma.sync) + scatter to per-head layout
    gemm_mma<0><<<dim3(N3 / 64, MROWS / 128), 256, GEMM_SMEM_BYTES>>>(
        gA_hi, gA_lo, gWqkv_hi, gWqkv_lo, b_qkv, (float*)nullptr, N3, HDIM);

    // 2) Flash attention (SIMT fp32)
    attn_kernel<<<dim3(FDIM / 128, BDIM * NHEAD), 256, ATTN_SMEM_BYTES>>>(g_ctx);

    // 3) Split ctx, then output projection on tensor cores
    split_kernel<<<(MROWS * HDIM / 4 + 255) / 256, 256>>>(g_ctx, gCtx_hi, gCtx_lo,
                                                          MROWS * HDIM / 4);
    gemm_mma<1><<<dim3(HDIM / 64, MROWS / 128), 256, GEMM_SMEM_BYTES>>>(
        gCtx_hi, gCtx_lo, gWout_hi, gWout_lo, (const float*)nullptr, out, HDIM, HDIM);

    // 4) b_out tail if harness packs the tuple (out, b_out)
    int tail = out_size - MROWS * HDIM;
    if (tail > 0) {
        int nvals = tail < HDIM ? tail : HDIM;
        tail_kernel<<<(nvals + 255) / 256, 256>>>(b_out, out + MROWS * HDIM, nvals);
    }
}

// round 6
// speedup vs baseline: 5.1923x; 5.1923x over previous
#include <cuda_runtime.h>
#include <cstdint>
#include <math.h>

// Problem dims
#define FDIM 2048
#define BDIM 2
#define HDIM 1024
#define NHEAD 16
#define EDIM 64
#define MROWS (FDIM * BDIM)      // 4096
#define N3 (3 * HDIM)            // 3072
#define MASK_ELEMS (BDIM * FDIM * FDIM)   // 8388608

typedef unsigned long long u64;

// ---------------------------------------------------------------------------
// Packed f32x2 helpers (baseline sm_100-family PTX, valid for compute_103)
// ---------------------------------------------------------------------------
__device__ __forceinline__ u64 pk2(float lo, float hi) {
    u64 r;
    asm("mov.b64 %0, {%1, %2};" : "=l"(r) : "f"(lo), "f"(hi));
    return r;
}
__device__ __forceinline__ void upk2(u64 p, float& lo, float& hi) {
    asm("mov.b64 {%0, %1}, %2;" : "=f"(lo), "=f"(hi) : "l"(p));
}
__device__ __forceinline__ void ffma2(u64& d, u64 a, u64 b) {
    asm("fma.rn.f32x2 %0, %1, %2, %0;" : "+l"(d) : "l"(a), "l"(b));
}
__device__ __forceinline__ void fmul2(u64& d, u64 a) {
    asm("mul.rn.f32x2 %0, %0, %1;" : "+l"(d) : "l"(a));
}

// ---------------------------------------------------------------------------
// Device scratch
// ---------------------------------------------------------------------------
__device__ float g_q[(size_t)BDIM * NHEAD * FDIM * EDIM];
__device__ float g_k[(size_t)BDIM * NHEAD * FDIM * EDIM];
__device__ float g_v[(size_t)BDIM * NHEAD * FDIM * EDIM];
__device__ float g_ctx[(size_t)MROWS * HDIM];
__device__ unsigned char g_mask[(size_t)MASK_ELEMS];
__device__ int g_mask_is_u8;

// ---------------------------------------------------------------------------
// Mask canonicalization (uint8-bool or int32-bool -> uint8)
// ---------------------------------------------------------------------------
__global__ void detect_mask_kernel(const unsigned int* __restrict__ raw)
{
    __shared__ int found;
    if (threadIdx.x == 0) found = 0;
    __syncthreads();
    int local = 0;
    for (int i = threadIdx.x; i < 4096; i += blockDim.x)
        if (raw[i] > 1u) local = 1;
    if (local) atomicOr(&found, 1);
    __syncthreads();
    if (threadIdx.x == 0) g_mask_is_u8 = found;
}

__global__ void convert_mask_kernel(const void* __restrict__ raw)
{
    int i4 = blockIdx.x * blockDim.x + threadIdx.x;
    if (i4 >= MASK_ELEMS / 4) return;
    uchar4 o;
    if (g_mask_is_u8) {
        o = ((const uchar4*)raw)[i4];
        o.x = o.x ? 1 : 0; o.y = o.y ? 1 : 0; o.z = o.z ? 1 : 0; o.w = o.w ? 1 : 0;
    } else {
        int4 v = ((const int4*)raw)[i4];
        o.x = v.x ? 1 : 0; o.y = v.y ? 1 : 0; o.z = v.z ? 1 : 0; o.w = v.w ? 1 : 0;
    }
    ((uchar4*)g_mask)[i4] = o;
}

// ---------------------------------------------------------------------------
// 128x128x16 SGEMM with packed fma.rn.f32x2.
// acc packed over column pairs: acc[i][jp] = (C[m][2jp], C[m][2jp+1]).
// A stored transposed + DUPLICATED in smem so (a,a) dup is one ld.b64.
// EPI==0: scatter + bias into g_q/g_k/g_v.  EPI==1: dense C (no bias).
// ---------------------------------------------------------------------------
#define AS2_STR 258
#define BS_STR 132

template <int EPI>
__global__ __launch_bounds__(256) void gemm128_f2(
    const float* __restrict__ A, const float* __restrict__ Bm,
    const float* __restrict__ bias, float* __restrict__ C,
    int Nn, int K)
{
    __shared__ float As2[16][AS2_STR];   // [k][2m] duplicated transposed A
    __shared__ float Bs[16][BS_STR];

    const int tid = threadIdx.x;
    const int tx = tid & 15, ty = tid >> 4;
    const int m0 = blockIdx.y * 128, n0 = blockIdx.x * 128;

    u64 acc[8][4];
#pragma unroll
    for (int i = 0; i < 8; i++)
#pragma unroll
        for (int j = 0; j < 4; j++) acc[i][j] = 0ull;

    for (int k0 = 0; k0 < K; k0 += 16) {
        // A tile 128x16 -> transposed + duplicated
#pragma unroll
        for (int p = 0; p < 2; p++) {
            int L = p * 256 + tid;
            int row = L >> 2, k4 = (L & 3) << 2;
            float4 v = *(const float4*)(A + (size_t)(m0 + row) * K + k0 + k4);
            As2[k4 + 0][2 * row] = v.x; As2[k4 + 0][2 * row + 1] = v.x;
            As2[k4 + 1][2 * row] = v.y; As2[k4 + 1][2 * row + 1] = v.y;
            As2[k4 + 2][2 * row] = v.z; As2[k4 + 2][2 * row + 1] = v.z;
            As2[k4 + 3][2 * row] = v.w; As2[k4 + 3][2 * row + 1] = v.w;
        }
        // B tile 16x128
#pragma unroll
        for (int p = 0; p < 2; p++) {
            int L = p * 256 + tid;
            int row = L >> 5, n4 = (L & 31) << 2;
            *(float4*)&Bs[row][n4] = *(const float4*)(Bm + (size_t)(k0 + row) * Nn + n0 + n4);
        }
        __syncthreads();

#pragma unroll
        for (int k = 0; k < 16; k++) {
            // b pairs: 8 consecutive cols = 4 native pairs
            u64 bp[4];
            {
                ulonglong2 q0 = *(const ulonglong2*)&Bs[k][tx * 8];
                ulonglong2 q1 = *(const ulonglong2*)&Bs[k][tx * 8 + 4];
                bp[0] = q0.x; bp[1] = q0.y; bp[2] = q1.x; bp[3] = q1.y;
            }
            // a dups: broadcast ld.b64 from duplicated As2
            u64 ad[8];
#pragma unroll
            for (int i = 0; i < 8; i++)
                ad[i] = *(const u64*)&As2[k][2 * (ty * 8 + i)];
#pragma unroll
            for (int i = 0; i < 8; i++)
#pragma unroll
                for (int j = 0; j < 4; j++)
                    ffma2(acc[i][j], ad[i], bp[j]);
        }
        __syncthreads();
    }

    // Epilogue
#pragma unroll
    for (int i = 0; i < 8; i++) {
        int m = m0 + ty * 8 + i;
        float c8[8];
#pragma unroll
        for (int j = 0; j < 4; j++) upk2(acc[i][j], c8[2 * j], c8[2 * j + 1]);
        if (EPI == 0) {
            int f = m >> 1, bb = m & 1;
#pragma unroll
            for (int j = 0; j < 8; j++) {
                int d = n0 + tx * 8 + j;
                int nh = d / 192;
                int r = d - nh * 192;
                int kind = r >> 6, e = r & 63;
                float val = c8[j] + __ldg(bias + d);
                float* dst = (kind == 0) ? g_q : (kind == 1) ? g_k : g_v;
                dst[(((bb << 4) + nh) * FDIM + f) * EDIM + e] = val;
            }
        } else {
            float* cp = C + (size_t)m * Nn + n0 + tx * 8;
            *(float4*)cp = make_float4(c8[0], c8[1], c8[2], c8[3]);
            *((float4*)cp + 1) = make_float4(c8[4], c8[5], c8[6], c8[7]);
        }
    }
}

// ---------------------------------------------------------------------------
// Flash attention with packed fma.rn.f32x2.
// One block = (head, 128-q-row tile); 256 threads; tx 0..15 cols, ty 0..15 rows.
// Packing over ROW pairs: QsT/PsT transposed so pairs are native ld.b64.
// ---------------------------------------------------------------------------
#define QT_STR 130
#define KT_STR 68
#define VS_STR 68
#define PT_STR 130
#define ATTN_SMEM_FLOATS (64 * QT_STR + 64 * KT_STR + 64 * VS_STR + 64 * PT_STR)
#define ATTN_SMEM_BYTES (ATTN_SMEM_FLOATS * 4)   // 101376

__global__ __launch_bounds__(256) void attn_kernel(float* __restrict__ ctxout)
{
    extern __shared__ float sm[];
    float* QsT = sm;                     // [e 64][m 128 +pad]  (transposed, scaled)
    float* KsT = QsT + 64 * QT_STR;      // [e 64][n 64 +pad]   (transposed)
    float* Vs  = KsT + 64 * KT_STR;      // [t 64][c 64 +pad]
    float* PsT = Vs + 64 * VS_STR;       // [t 64][m 128 +pad]  (transposed)

    const int tid = threadIdx.x;
    const int tx = tid & 15, ty = tid >> 4;
    const int head = blockIdx.y;
    const int b = head >> 4, n = head & 15;
    const int f0 = blockIdx.x * 128;

    const float* qh = g_q + (size_t)head * FDIM * EDIM;
    const float* kh = g_k + (size_t)head * FDIM * EDIM;
    const float* vh = g_v + (size_t)head * FDIM * EDIM;
    const unsigned char* mbase = g_mask + (size_t)b * FDIM * FDIM;

    // Load Q tile, scaled by 1/8, TRANSPOSED into QsT[e][m]
#pragma unroll
    for (int p = 0; p < 8; p++) {
        int L = p * 256 + tid;
        int r = L >> 4, c4 = (L & 15) << 2;
        float4 v = *(const float4*)(qh + (size_t)(f0 + r) * EDIM + c4);
        QsT[(c4 + 0) * QT_STR + r] = v.x * 0.125f;
        QsT[(c4 + 1) * QT_STR + r] = v.y * 0.125f;
        QsT[(c4 + 2) * QT_STR + r] = v.z * 0.125f;
        QsT[(c4 + 3) * QT_STR + r] = v.w * 0.125f;
    }

    float mrow[8], lrow[8];
    u64 cacc[4][4];   // row-pairs (2ii, 2ii+1) x cols tx*4+c
#pragma unroll
    for (int i = 0; i < 8; i++) { mrow[i] = -1e30f; lrow[i] = 0.0f; }
#pragma unroll
    for (int ii = 0; ii < 4; ii++)
#pragma unroll
        for (int c = 0; c < 4; c++) cacc[ii][c] = 0ull;

    for (int t0 = 0; t0 < FDIM; t0 += 64) {
        // Load K (transposed into KsT[e][t]) and V (row-major Vs[t][c])
#pragma unroll
        for (int p = 0; p < 4; p++) {
            int L = p * 256 + tid;
            int r = L >> 4, c4 = (L & 15) << 2;
            float4 kv = *(const float4*)(kh + (size_t)(t0 + r) * EDIM + c4);
            KsT[(c4 + 0) * KT_STR + r] = kv.x;
            KsT[(c4 + 1) * KT_STR + r] = kv.y;
            KsT[(c4 + 2) * KT_STR + r] = kv.z;
            KsT[(c4 + 3) * KT_STR + r] = kv.w;
            float4 vv = *(const float4*)(vh + (size_t)(t0 + r) * EDIM + c4);
            *(float4*)&Vs[r * VS_STR + c4] = vv;
        }
        __syncthreads();

        // ---- S = Q K^T : packed over row pairs ----
        u64 sacc[4][4];
#pragma unroll
        for (int ii = 0; ii < 4; ii++)
#pragma unroll
            for (int j = 0; j < 4; j++) sacc[ii][j] = 0ull;

#pragma unroll 4
        for (int e = 0; e < 64; e++) {
            u64 qp[4];
#pragma unroll
            for (int ii = 0; ii < 4; ii++)
                qp[ii] = *(const u64*)&QsT[e * QT_STR + ty * 8 + 2 * ii];
            float4 kf = *(const float4*)&KsT[e * KT_STR + tx * 4];
            u64 kd[4] = {pk2(kf.x, kf.x), pk2(kf.y, kf.y),
                         pk2(kf.z, kf.z), pk2(kf.w, kf.w)};
#pragma unroll
            for (int ii = 0; ii < 4; ii++)
#pragma unroll
                for (int j = 0; j < 4; j++)
                    ffma2(sacc[ii][j], qp[ii], kd[j]);
        }

        // unpack to scalar rows
        float s[8][4];
#pragma unroll
        for (int ii = 0; ii < 4; ii++)
#pragma unroll
            for (int j = 0; j < 4; j++)
                upk2(sacc[ii][j], s[2 * ii][j], s[2 * ii + 1][j]);

        // ---- mask + online softmax (scalar, per row) ----
        float corr[8];
#pragma unroll
        for (int i = 0; i < 8; i++) {
            int f = f0 + ty * 8 + i;
            uchar4 mv = *(const uchar4*)(mbase + (size_t)f * FDIM + t0 + tx * 4);
            if (!mv.x) s[i][0] = -10000.0f;
            if (!mv.y) s[i][1] = -10000.0f;
            if (!mv.z) s[i][2] = -10000.0f;
            if (!mv.w) s[i][3] = -10000.0f;

            float mt = fmaxf(fmaxf(s[i][0], s[i][1]), fmaxf(s[i][2], s[i][3]));
#pragma unroll
            for (int o = 1; o < 16; o <<= 1)
                mt = fmaxf(mt, __shfl_xor_sync(0xffffffffu, mt, o));

            float mnew = fmaxf(mrow[i], mt);
            corr[i] = __expf(mrow[i] - mnew);
            mrow[i] = mnew;

            float ps = 0.0f;
#pragma unroll
            for (int j = 0; j < 4; j++) {
                s[i][j] = __expf(s[i][j] - mnew);
                ps += s[i][j];
            }
#pragma unroll
            for (int o = 1; o < 16; o <<= 1)
                ps += __shfl_xor_sync(0xffffffffu, ps, o);

            lrow[i] = lrow[i] * corr[i] + ps;

            // store P transposed: PsT[t][m]
#pragma unroll
            for (int j = 0; j < 4; j++)
                PsT[(tx * 4 + j) * PT_STR + ty * 8 + i] = s[i][j];
        }

        // rescale accumulated context by correction (packed row pairs)
#pragma unroll
        for (int ii = 0; ii < 4; ii++) {
            u64 cp = pk2(corr[2 * ii], corr[2 * ii + 1]);
#pragma unroll
            for (int c = 0; c < 4; c++) fmul2(cacc[ii][c], cp);
        }
        __syncthreads();

        // ---- ctx += P V : packed over row pairs ----
#pragma unroll 4
        for (int t = 0; t < 64; t++) {
            u64 pp[4];
#pragma unroll
            for (int ii = 0; ii < 4; ii++)
                pp[ii] = *(const u64*)&PsT[t * PT_STR + ty * 8 + 2 * ii];
            float4 vf = *(const float4*)&Vs[t * VS_STR + tx * 4];
            u64 vd[4] = {pk2(vf.x, vf.x), pk2(vf.y, vf.y),
                         pk2(vf.z, vf.z), pk2(vf.w, vf.w)};
#pragma unroll
            for (int ii = 0; ii < 4; ii++)
#pragma unroll
                for (int c = 0; c < 4; c++)
                    ffma2(cacc[ii][c], pp[ii], vd[c]);
        }
        __syncthreads();
    }

    // Normalize and write ctx: [f][b][n*64 + c]
#pragma unroll
    for (int ii = 0; ii < 4; ii++) {
        float r0c[4], r1c[4];
#pragma unroll
        for (int c = 0; c < 4; c++) upk2(cacc[ii][c], r0c[c], r1c[c]);
#pragma unroll
        for (int h = 0; h < 2; h++) {
            int i = 2 * ii + h;
            float inv = 1.0f / lrow[i];
            int f = f0 + ty * 8 + i;
            const float* rc = h ? r1c : r0c;
            float4 o = make_float4(rc[0] * inv, rc[1] * inv, rc[2] * inv, rc[3] * inv);
            *(float4*)(ctxout + ((size_t)f * BDIM + b) * HDIM + n * EDIM + tx * 4) = o;
        }
    }
}

__global__ void tail_kernel(const float* __restrict__ b_out,
                            float* __restrict__ dst, int nvals)
{
    int i = blockIdx.x * blockDim.x + threadIdx.x;
    if (i < nvals) dst[i] = b_out[i];
}

extern "C" void kernel_launch(void* const* d_in, const int* in_sizes, int n_in,
                              void* d_out, int out_size)
{
    // Identify inputs by unique element counts
    const float* q_input = nullptr;
    const void* mask_raw = nullptr;
    const float* w_qkv = nullptr;
    const float* b_qkv = nullptr;
    const float* w_out = nullptr;
    const float* b_out = nullptr;
    for (int i = 0; i < n_in; i++) {
        switch (in_sizes[i]) {
            case 4194304: q_input = (const float*)d_in[i]; break;
            case 8388608: mask_raw = d_in[i]; break;
            case 3145728: w_qkv = (const float*)d_in[i]; break;
            case 3072:    b_qkv = (const float*)d_in[i]; break;
            case 1048576: w_out = (const float*)d_in[i]; break;
            case 1024:    b_out = (const float*)d_in[i]; break;
            default: break;
        }
    }
    float* out = (float*)d_out;

    cudaFuncSetAttribute(attn_kernel, cudaFuncAttributeMaxDynamicSharedMemorySize,
                         ATTN_SMEM_BYTES);

    // 0) Mask canonicalization
    detect_mask_kernel<<<1, 256>>>((const unsigned int*)mask_raw);
    convert_mask_kernel<<<(MASK_ELEMS / 4 + 255) / 256, 256>>>(mask_raw);

    // 1) QKV projection (packed-FFMA2 SGEMM) + scatter to per-head layout
    gemm128_f2<0><<<dim3(N3 / 128, MROWS / 128), 256>>>(
        q_input, w_qkv, b_qkv, (float*)nullptr, N3, HDIM);

    // 2) Flash attention (packed-FFMA2 inner loops)
    attn_kernel<<<dim3(FDIM / 128, BDIM * NHEAD), 256, ATTN_SMEM_BYTES>>>(g_ctx);

    // 3) Output projection (no bias)
    gemm128_f2<1><<<dim3(HDIM / 128, MROWS / 128), 256>>>(
        g_ctx, w_out, (const float*)nullptr, out, HDIM, HDIM);

    // 4) b_out tail if harness packs the tuple (out, b_out)
    int tail = out_size - MROWS * HDIM;
    if (tail > 0) {
        int nvals = tail < HDIM ? tail : HDIM;
        tail_kernel<<<(nvals + 255) / 256, 256>>>(b_out, out + MROWS * HDIM, nvals);
    }
}